// round 1
// baseline (speedup 1.0000x reference)
#include <cuda_runtime.h>

#define NNODES 50000
#define NEDGES 600000
#define HFEAT  128
#define NCLASS 40
#define NEG_SLOPE 0.1f

// ---------------- device scratch (static, allocation-free) ----------------
__device__ int   g_deg[NNODES];
__device__ int   g_fill[NNODES];
__device__ int   g_rowptr[NNODES + 1];
__device__ int   g_col[NEDGES];
__device__ float g_inv[NNODES];
__device__ float g_agg[(size_t)NNODES * HFEAT];
__device__ float g_hA [(size_t)NNODES * HFEAT];
__device__ float g_hB [(size_t)NNODES * HFEAT];

// ---------------- CSR build ----------------
__global__ void k_zero() {
    int i = blockIdx.x * blockDim.x + threadIdx.x;
    if (i < NNODES) { g_deg[i] = 0; g_fill[i] = 0; }
}

__global__ void k_hist(const int* __restrict__ ei) {
    int e = blockIdx.x * blockDim.x + threadIdx.x;
    if (e < NEDGES) atomicAdd(&g_deg[ei[NEDGES + e]], 1);
}

// single-block exclusive scan over degrees; also compute 1/max(deg,1)
__global__ void k_scan() {
    __shared__ int sh[1024];
    int t = threadIdx.x;
    int carry = 0;
    for (int base = 0; base < NNODES; base += 1024) {
        int idx = base + t;
        int v = (idx < NNODES) ? g_deg[idx] : 0;
        sh[t] = v;
        __syncthreads();
        #pragma unroll
        for (int off = 1; off < 1024; off <<= 1) {
            int y = (t >= off) ? sh[t - off] : 0;
            __syncthreads();
            sh[t] += y;
            __syncthreads();
        }
        int incl = sh[t];
        if (idx < NNODES) {
            g_rowptr[idx] = carry + incl - v;
            g_inv[idx] = 1.0f / fmaxf((float)v, 1.0f);
        }
        int total = sh[1023];
        __syncthreads();
        carry += total;
    }
    if (t == 0) g_rowptr[NNODES] = carry;
}

__global__ void k_fill(const int* __restrict__ ei) {
    int e = blockIdx.x * blockDim.x + threadIdx.x;
    if (e < NEDGES) {
        int dst = ei[NEDGES + e];
        int pos = g_rowptr[dst] + atomicAdd(&g_fill[dst], 1);
        g_col[pos] = ei[e];
    }
}

// ---------------- mean aggregation: warp per destination node ----------------
__global__ void k_aggregate(const float* __restrict__ in, float* __restrict__ out) {
    int gw   = (blockIdx.x * blockDim.x + threadIdx.x) >> 5;
    int lane = threadIdx.x & 31;
    if (gw >= NNODES) return;
    int s = g_rowptr[gw], e = g_rowptr[gw + 1];
    float4 acc = make_float4(0.f, 0.f, 0.f, 0.f);
    int i = s;
    for (; i + 1 < e; i += 2) {
        int s0 = g_col[i], s1 = g_col[i + 1];
        float4 v0 = *(const float4*)(in + (size_t)s0 * HFEAT + lane * 4);
        float4 v1 = *(const float4*)(in + (size_t)s1 * HFEAT + lane * 4);
        acc.x += v0.x + v1.x; acc.y += v0.y + v1.y;
        acc.z += v0.z + v1.z; acc.w += v0.w + v1.w;
    }
    if (i < e) {
        int s0 = g_col[i];
        float4 v0 = *(const float4*)(in + (size_t)s0 * HFEAT + lane * 4);
        acc.x += v0.x; acc.y += v0.y; acc.z += v0.z; acc.w += v0.w;
    }
    float inv = g_inv[gw];
    float4 r = make_float4(acc.x * inv, acc.y * inv, acc.z * inv, acc.w * inv);
    *(float4*)(out + (size_t)gw * HFEAT + lane * 4) = r;
}

// ---------------- fused SAGE GEMM: out = act([A1|A2] @ [W1;W2] + b), Nout=128 ----------------
__global__ void __launch_bounds__(256, 2) k_gemm128(
    const float* __restrict__ A1, const float* __restrict__ A2,
    const float* __restrict__ W1, const float* __restrict__ W2,
    const float* __restrict__ bias, float* __restrict__ out)
{
    __shared__ float As[8][128];
    __shared__ float Bs[8][128];
    int t = threadIdx.x;
    int block_row = blockIdx.x * 128;
    int tm = (t >> 4) << 3;
    int tn = (t & 15) << 3;
    float acc[8][8];
    #pragma unroll
    for (int i = 0; i < 8; i++)
        #pragma unroll
        for (int j = 0; j < 8; j++) acc[i][j] = 0.f;

    int lrow = t >> 1;
    int lseg = (t & 1) << 2;
    int grow = block_row + lrow;
    bool rok = grow < NNODES;
    int bk = t >> 5;
    int bc = (t & 31) << 2;

    #pragma unroll 1
    for (int phase = 0; phase < 2; ++phase) {
        const float* A = phase ? A2 : A1;
        const float* W = phase ? W2 : W1;
        #pragma unroll 1
        for (int k0 = 0; k0 < 128; k0 += 8) {
            float4 av = rok ? *(const float4*)(A + (size_t)grow * 128 + k0 + lseg)
                            : make_float4(0.f, 0.f, 0.f, 0.f);
            float4 bv = *(const float4*)(W + (size_t)(k0 + bk) * 128 + bc);
            As[lseg + 0][lrow] = av.x; As[lseg + 1][lrow] = av.y;
            As[lseg + 2][lrow] = av.z; As[lseg + 3][lrow] = av.w;
            *(float4*)&Bs[bk][bc] = bv;
            __syncthreads();
            #pragma unroll
            for (int k = 0; k < 8; k++) {
                float a[8], b[8];
                #pragma unroll
                for (int i = 0; i < 8; i++) a[i] = As[k][tm + i];
                #pragma unroll
                for (int j = 0; j < 8; j++) b[j] = Bs[k][tn + j];
                #pragma unroll
                for (int i = 0; i < 8; i++)
                    #pragma unroll
                    for (int j = 0; j < 8; j++)
                        acc[i][j] = fmaf(a[i], b[j], acc[i][j]);
            }
            __syncthreads();
        }
    }
    #pragma unroll
    for (int i = 0; i < 8; i++) {
        int r = block_row + tm + i;
        if (r >= NNODES) break;
        #pragma unroll
        for (int j = 0; j < 8; j++) {
            float v = acc[i][j] + bias[tn + j];
            v = v > 0.f ? v : NEG_SLOPE * v;
            out[(size_t)r * 128 + tn + j] = v;
        }
    }
}

// ---------------- decoder GEMM: Nout=40, no activation ----------------
__global__ void __launch_bounds__(256, 2) k_gemm_dec(
    const float* __restrict__ A1, const float* __restrict__ A2,
    const float* __restrict__ W1, const float* __restrict__ W2,
    const float* __restrict__ bias, float* __restrict__ out)
{
    __shared__ float As[8][128];
    __shared__ float Bs[8][40];
    int t = threadIdx.x;
    int block_row = blockIdx.x * 128;
    int tm = (t >> 3) << 2;     // 0..124 step 4
    int tn = (t & 7) * 5;       // 0..35
    float acc[4][5];
    #pragma unroll
    for (int i = 0; i < 4; i++)
        #pragma unroll
        for (int j = 0; j < 5; j++) acc[i][j] = 0.f;

    int lrow = t >> 1;
    int lseg = (t & 1) << 2;
    int grow = block_row + lrow;
    bool rok = grow < NNODES;

    #pragma unroll 1
    for (int phase = 0; phase < 2; ++phase) {
        const float* A = phase ? A2 : A1;
        const float* W = phase ? W2 : W1;
        #pragma unroll 1
        for (int k0 = 0; k0 < 128; k0 += 8) {
            float4 av = rok ? *(const float4*)(A + (size_t)grow * 128 + k0 + lseg)
                            : make_float4(0.f, 0.f, 0.f, 0.f);
            As[lseg + 0][lrow] = av.x; As[lseg + 1][lrow] = av.y;
            As[lseg + 2][lrow] = av.z; As[lseg + 3][lrow] = av.w;
            for (int idx = t; idx < 320; idx += 256)
                Bs[idx / 40][idx % 40] = W[(size_t)(k0 + idx / 40) * 40 + idx % 40];
            __syncthreads();
            #pragma unroll
            for (int k = 0; k < 8; k++) {
                float a[4], b[5];
                #pragma unroll
                for (int i = 0; i < 4; i++) a[i] = As[k][tm + i];
                #pragma unroll
                for (int j = 0; j < 5; j++) b[j] = Bs[k][tn + j];
                #pragma unroll
                for (int i = 0; i < 4; i++)
                    #pragma unroll
                    for (int j = 0; j < 5; j++)
                        acc[i][j] = fmaf(a[i], b[j], acc[i][j]);
            }
            __syncthreads();
        }
    }
    #pragma unroll
    for (int i = 0; i < 4; i++) {
        int r = block_row + tm + i;
        if (r >= NNODES) break;
        #pragma unroll
        for (int j = 0; j < 5; j++) {
            out[(size_t)r * NCLASS + tn + j] = acc[i][j] + bias[tn + j];
        }
    }
}

// ---------------- log_softmax in place, warp per row ----------------
__global__ void k_logsoftmax(float* __restrict__ out) {
    int w    = (blockIdx.x * blockDim.x + threadIdx.x) >> 5;
    int lane = threadIdx.x & 31;
    if (w >= NNODES) return;
    float* row = out + (size_t)w * NCLASS;
    float v0 = (lane < NCLASS)      ? row[lane]      : -1e30f;
    float v1 = (lane + 32 < NCLASS) ? row[lane + 32] : -1e30f;
    float m = fmaxf(v0, v1);
    #pragma unroll
    for (int o = 16; o; o >>= 1) m = fmaxf(m, __shfl_xor_sync(0xFFFFFFFFu, m, o));
    float s = ((lane < NCLASS) ? expf(v0 - m) : 0.f) +
              ((lane + 32 < NCLASS) ? expf(v1 - m) : 0.f);
    #pragma unroll
    for (int o = 16; o; o >>= 1) s += __shfl_xor_sync(0xFFFFFFFFu, s, o);
    float l = m + logf(s);
    if (lane < NCLASS)      row[lane]      = v0 - l;
    if (lane + 32 < NCLASS) row[lane + 32] = v1 - l;
}

// ---------------- launch ----------------
extern "C" void kernel_launch(void* const* d_in, const int* in_sizes, int n_in,
                              void* d_out, int out_size) {
    const float* x      = (const float*)d_in[0];
    const int*   ei     = (const int*)  d_in[1];
    const float* enc_Wl = (const float*)d_in[2];
    const float* enc_Wr = (const float*)d_in[3];
    const float* enc_b  = (const float*)d_in[4];
    const float* lay_Wl = (const float*)d_in[5];
    const float* lay_Wr = (const float*)d_in[6];
    const float* lay_b  = (const float*)d_in[7];
    const float* dec_Wl = (const float*)d_in[8];
    const float* dec_Wr = (const float*)d_in[9];
    const float* dec_b  = (const float*)d_in[10];
    float* out = (float*)d_out;

    float *agg, *hA, *hB;
    cudaGetSymbolAddress((void**)&agg, g_agg);
    cudaGetSymbolAddress((void**)&hA,  g_hA);
    cudaGetSymbolAddress((void**)&hB,  g_hB);

    const int ZB = (NNODES + 255) / 256;
    const int EB = (NEDGES + 255) / 256;
    const int AGGB = (NNODES * 32 + 255) / 256;   // warp per node
    const int MB = (NNODES + 127) / 128;          // 391 GEMM row-tiles

    k_zero<<<ZB, 256>>>();
    k_hist<<<EB, 256>>>(ei);
    k_scan<<<1, 1024>>>();
    k_fill<<<EB, 256>>>(ei);

    // encoder
    k_aggregate<<<AGGB, 256>>>(x, agg);
    k_gemm128<<<MB, 256>>>(agg, x, enc_Wl, enc_Wr, enc_b, hA);
    // layer 0
    k_aggregate<<<AGGB, 256>>>(hA, agg);
    k_gemm128<<<MB, 256>>>(agg, hA, lay_Wl, lay_Wr, lay_b, hB);
    // layer 1
    k_aggregate<<<AGGB, 256>>>(hB, agg);
    k_gemm128<<<MB, 256>>>(agg, hB, lay_Wl + HFEAT * HFEAT, lay_Wr + HFEAT * HFEAT,
                           lay_b + HFEAT, hA);
    // decoder + log_softmax
    k_aggregate<<<AGGB, 256>>>(hA, agg);
    k_gemm_dec<<<MB, 256>>>(agg, hA, dec_Wl, dec_Wr, dec_b, out);
    k_logsoftmax<<<AGGB, 256>>>(out);
}

// round 3
// speedup vs baseline: 1.3533x; 1.3533x over previous
#include <cuda_runtime.h>

#define NNODES 50000
#define NEDGES 600000
#define HFEAT  128
#define NCLASS 40
#define NEG_SLOPE 0.1f

// ---------------- device scratch (static, allocation-free) ----------------
__device__ int   g_deg[NNODES];
__device__ int   g_fill[NNODES];
__device__ int   g_rowptr[NNODES + 1];
__device__ int   g_col[NEDGES];
__device__ float g_inv[NNODES];
__device__ float g_agg[(size_t)NNODES * HFEAT];
__device__ float g_hA [(size_t)NNODES * HFEAT];
__device__ float g_hB [(size_t)NNODES * HFEAT];

// ---------------- helpers ----------------
__device__ __forceinline__ void tf32_split(float v, unsigned& hi, unsigned& lo) {
    unsigned h;
    asm("cvt.rna.tf32.f32 %0, %1;" : "=r"(h) : "f"(v));
    float hf = __uint_as_float(h);
    float lf = v - hf;
    unsigned l;
    asm("cvt.rna.tf32.f32 %0, %1;" : "=r"(l) : "f"(lf));
    hi = h; lo = l;
}

__device__ __forceinline__ void mma_tf32(float* d, const unsigned* a, unsigned b0, unsigned b1) {
    asm volatile(
        "mma.sync.aligned.m16n8k8.row.col.f32.tf32.tf32.f32 "
        "{%0,%1,%2,%3}, {%4,%5,%6,%7}, {%8,%9}, {%0,%1,%2,%3};"
        : "+f"(d[0]), "+f"(d[1]), "+f"(d[2]), "+f"(d[3])
        : "r"(a[0]), "r"(a[1]), "r"(a[2]), "r"(a[3]), "r"(b0), "r"(b1));
}

// ---------------- CSR build ----------------
__global__ void k_zero() {
    int i = blockIdx.x * blockDim.x + threadIdx.x;
    if (i < NNODES) { g_deg[i] = 0; g_fill[i] = 0; }
}

__global__ void k_hist(const int* __restrict__ ei) {
    int e = blockIdx.x * blockDim.x + threadIdx.x;
    if (e < NEDGES) atomicAdd(&g_deg[ei[NEDGES + e]], 1);
}

__global__ void k_scan() {
    __shared__ int sh[1024];
    int t = threadIdx.x;
    int carry = 0;
    for (int base = 0; base < NNODES; base += 1024) {
        int idx = base + t;
        int v = (idx < NNODES) ? g_deg[idx] : 0;
        sh[t] = v;
        __syncthreads();
        #pragma unroll
        for (int off = 1; off < 1024; off <<= 1) {
            int y = (t >= off) ? sh[t - off] : 0;
            __syncthreads();
            sh[t] += y;
            __syncthreads();
        }
        int incl = sh[t];
        if (idx < NNODES) {
            g_rowptr[idx] = carry + incl - v;
            g_inv[idx] = 1.0f / fmaxf((float)v, 1.0f);
        }
        int total = sh[1023];
        __syncthreads();
        carry += total;
    }
    if (t == 0) g_rowptr[NNODES] = carry;
}

__global__ void k_fill(const int* __restrict__ ei) {
    int e = blockIdx.x * blockDim.x + threadIdx.x;
    if (e < NEDGES) {
        int dst = ei[NEDGES + e];
        int pos = g_rowptr[dst] + atomicAdd(&g_fill[dst], 1);
        g_col[pos] = ei[e];
    }
}

// ---------------- mean aggregation: warp per destination node ----------------
__global__ void k_aggregate(const float* __restrict__ in, float* __restrict__ out) {
    int gw   = (blockIdx.x * blockDim.x + threadIdx.x) >> 5;
    int lane = threadIdx.x & 31;
    if (gw >= NNODES) return;
    int s = g_rowptr[gw], e = g_rowptr[gw + 1];
    float4 acc = make_float4(0.f, 0.f, 0.f, 0.f);
    int i = s;
    for (; i + 1 < e; i += 2) {
        int s0 = g_col[i], s1 = g_col[i + 1];
        float4 v0 = *(const float4*)(in + (size_t)s0 * HFEAT + lane * 4);
        float4 v1 = *(const float4*)(in + (size_t)s1 * HFEAT + lane * 4);
        acc.x += v0.x + v1.x; acc.y += v0.y + v1.y;
        acc.z += v0.z + v1.z; acc.w += v0.w + v1.w;
    }
    if (i < e) {
        int s0 = g_col[i];
        float4 v0 = *(const float4*)(in + (size_t)s0 * HFEAT + lane * 4);
        acc.x += v0.x; acc.y += v0.y; acc.z += v0.z; acc.w += v0.w;
    }
    float inv = g_inv[gw];
    float4 r = make_float4(acc.x * inv, acc.y * inv, acc.z * inv, acc.w * inv);
    *(float4*)(out + (size_t)gw * HFEAT + lane * 4) = r;
}

// ---------------- SAGE GEMM, 3xTF32 tensor-core: out = act([A1|A2]@[W1;W2]+b), N=128 ----------------
#define ASTR 20
#define BSTR 132

__global__ void __launch_bounds__(256, 2) k_gemm128(
    const float* __restrict__ A1, const float* __restrict__ A2,
    const float* __restrict__ W1, const float* __restrict__ W2,
    const float* __restrict__ bias, float* __restrict__ out)
{
    __shared__ unsigned As_hi[128 * ASTR];
    __shared__ unsigned As_lo[128 * ASTR];
    __shared__ unsigned Bs_hi[16 * BSTR];
    __shared__ unsigned Bs_lo[16 * BSTR];

    int t = threadIdx.x;
    int lane = t & 31;
    int w = t >> 5;
    int rg = w >> 1;      // row group 0..3 (32 rows each)
    int cg = w & 1;       // col group 0..1 (64 cols each)
    int block_row = blockIdx.x * 128;

    float acc[2][8][4];
    #pragma unroll
    for (int i = 0; i < 2; i++)
        #pragma unroll
        for (int j = 0; j < 8; j++)
            #pragma unroll
            for (int q = 0; q < 4; q++) acc[i][j][q] = 0.f;

    #pragma unroll 1
    for (int phase = 0; phase < 2; ++phase) {
        const float* A = phase ? A2 : A1;
        const float* W = phase ? W2 : W1;
        #pragma unroll 1
        for (int k0 = 0; k0 < 128; k0 += 16) {
            __syncthreads();
            // stage A chunk: 128 rows x 16 cols
            #pragma unroll
            for (int i = 0; i < 2; i++) {
                int idx = t + (i << 8);
                int r = idx >> 2, kk = (idx & 3) << 2;
                int gr = block_row + r;
                float4 v = (gr < NNODES) ? *(const float4*)(A + (size_t)gr * 128 + k0 + kk)
                                         : make_float4(0.f, 0.f, 0.f, 0.f);
                uint4 h, l;
                tf32_split(v.x, h.x, l.x);
                tf32_split(v.y, h.y, l.y);
                tf32_split(v.z, h.z, l.z);
                tf32_split(v.w, h.w, l.w);
                *(uint4*)&As_hi[r * ASTR + kk] = h;
                *(uint4*)&As_lo[r * ASTR + kk] = l;
            }
            // stage B chunk: 16 rows x 128 cols
            #pragma unroll
            for (int i = 0; i < 2; i++) {
                int idx = t + (i << 8);
                int kk = idx >> 5, n = (idx & 31) << 2;
                float4 v = *(const float4*)(W + (size_t)(k0 + kk) * 128 + n);
                uint4 h, l;
                tf32_split(v.x, h.x, l.x);
                tf32_split(v.y, h.y, l.y);
                tf32_split(v.z, h.z, l.z);
                tf32_split(v.w, h.w, l.w);
                *(uint4*)&Bs_hi[kk * BSTR + n] = h;
                *(uint4*)&Bs_lo[kk * BSTR + n] = l;
            }
            __syncthreads();

            #pragma unroll
            for (int ks = 0; ks < 2; ks++) {
                unsigned ah[2][4], al[2][4];
                int kc = (ks << 3) + (lane & 3);
                int rb = (rg << 5) + (lane >> 2);
                #pragma unroll
                for (int i = 0; i < 2; i++) {
                    int r0 = rb + (i << 4);
                    ah[i][0] = As_hi[r0 * ASTR + kc];
                    ah[i][1] = As_hi[(r0 + 8) * ASTR + kc];
                    ah[i][2] = As_hi[r0 * ASTR + kc + 4];
                    ah[i][3] = As_hi[(r0 + 8) * ASTR + kc + 4];
                    al[i][0] = As_lo[r0 * ASTR + kc];
                    al[i][1] = As_lo[(r0 + 8) * ASTR + kc];
                    al[i][2] = As_lo[r0 * ASTR + kc + 4];
                    al[i][3] = As_lo[(r0 + 8) * ASTR + kc + 4];
                }
                #pragma unroll
                for (int j = 0; j < 8; j++) {
                    int n0 = (cg << 6) + (j << 3) + (lane >> 2);
                    int kb = (ks << 3) + (lane & 3);
                    unsigned bh0 = Bs_hi[kb * BSTR + n0];
                    unsigned bh1 = Bs_hi[(kb + 4) * BSTR + n0];
                    unsigned bl0 = Bs_lo[kb * BSTR + n0];
                    unsigned bl1 = Bs_lo[(kb + 4) * BSTR + n0];
                    #pragma unroll
                    for (int i = 0; i < 2; i++) {
                        mma_tf32(acc[i][j], al[i], bh0, bh1);
                        mma_tf32(acc[i][j], ah[i], bl0, bl1);
                        mma_tf32(acc[i][j], ah[i], bh0, bh1);
                    }
                }
            }
        }
    }

    // epilogue: bias + leaky relu
    #pragma unroll
    for (int i = 0; i < 2; i++) {
        int r0 = block_row + (rg << 5) + (i << 4) + (lane >> 2);
        #pragma unroll
        for (int j = 0; j < 8; j++) {
            int c = (cg << 6) + (j << 3) + ((lane & 3) << 1);
            float bi0 = bias[c], bi1 = bias[c + 1];
            if (r0 < NNODES) {
                float v0 = acc[i][j][0] + bi0;
                float v1 = acc[i][j][1] + bi1;
                v0 = v0 > 0.f ? v0 : NEG_SLOPE * v0;
                v1 = v1 > 0.f ? v1 : NEG_SLOPE * v1;
                out[(size_t)r0 * 128 + c] = v0;
                out[(size_t)r0 * 128 + c + 1] = v1;
            }
            int r1 = r0 + 8;
            if (r1 < NNODES) {
                float v2 = acc[i][j][2] + bi0;
                float v3 = acc[i][j][3] + bi1;
                v2 = v2 > 0.f ? v2 : NEG_SLOPE * v2;
                v3 = v3 > 0.f ? v3 : NEG_SLOPE * v3;
                out[(size_t)r1 * 128 + c] = v2;
                out[(size_t)r1 * 128 + c + 1] = v3;
            }
        }
    }
}

// ---------------- decoder GEMM, 3xTF32: Nout=40, no activation ----------------
#define BSTRD 44

__global__ void __launch_bounds__(256, 2) k_gemm_dec(
    const float* __restrict__ A1, const float* __restrict__ A2,
    const float* __restrict__ W1, const float* __restrict__ W2,
    const float* __restrict__ bias, float* __restrict__ out)
{
    __shared__ unsigned As_hi[128 * ASTR];
    __shared__ unsigned As_lo[128 * ASTR];
    __shared__ unsigned Bs_hi[16 * BSTRD];
    __shared__ unsigned Bs_lo[16 * BSTRD];

    int t = threadIdx.x;
    int lane = t & 31;
    int w = t >> 5;               // warp 0..7, owns 16 rows
    int block_row = blockIdx.x * 128;

    float acc[5][4];
    #pragma unroll
    for (int j = 0; j < 5; j++)
        #pragma unroll
        for (int q = 0; q < 4; q++) acc[j][q] = 0.f;

    #pragma unroll 1
    for (int phase = 0; phase < 2; ++phase) {
        const float* A = phase ? A2 : A1;
        const float* W = phase ? W2 : W1;
        #pragma unroll 1
        for (int k0 = 0; k0 < 128; k0 += 16) {
            __syncthreads();
            #pragma unroll
            for (int i = 0; i < 2; i++) {
                int idx = t + (i << 8);
                int r = idx >> 2, kk = (idx & 3) << 2;
                int gr = block_row + r;
                float4 v = (gr < NNODES) ? *(const float4*)(A + (size_t)gr * 128 + k0 + kk)
                                         : make_float4(0.f, 0.f, 0.f, 0.f);
                uint4 h, l;
                tf32_split(v.x, h.x, l.x);
                tf32_split(v.y, h.y, l.y);
                tf32_split(v.z, h.z, l.z);
                tf32_split(v.w, h.w, l.w);
                *(uint4*)&As_hi[r * ASTR + kk] = h;
                *(uint4*)&As_lo[r * ASTR + kk] = l;
            }
            if (t < 160) {
                int kk = t / 10, n = (t % 10) << 2;
                float4 v = *(const float4*)(W + (size_t)(k0 + kk) * NCLASS + n);
                uint4 h, l;
                tf32_split(v.x, h.x, l.x);
                tf32_split(v.y, h.y, l.y);
                tf32_split(v.z, h.z, l.z);
                tf32_split(v.w, h.w, l.w);
                *(uint4*)&Bs_hi[kk * BSTRD + n] = h;
                *(uint4*)&Bs_lo[kk * BSTRD + n] = l;
            }
            __syncthreads();

            #pragma unroll
            for (int ks = 0; ks < 2; ks++) {
                unsigned ah[4], al[4];
                int kc = (ks << 3) + (lane & 3);
                int r0 = (w << 4) + (lane >> 2);
                ah[0] = As_hi[r0 * ASTR + kc];
                ah[1] = As_hi[(r0 + 8) * ASTR + kc];
                ah[2] = As_hi[r0 * ASTR + kc + 4];
                ah[3] = As_hi[(r0 + 8) * ASTR + kc + 4];
                al[0] = As_lo[r0 * ASTR + kc];
                al[1] = As_lo[(r0 + 8) * ASTR + kc];
                al[2] = As_lo[r0 * ASTR + kc + 4];
                al[3] = As_lo[(r0 + 8) * ASTR + kc + 4];
                #pragma unroll
                for (int j = 0; j < 5; j++) {
                    int n0 = (j << 3) + (lane >> 2);
                    int kb = (ks << 3) + (lane & 3);
                    unsigned bh0 = Bs_hi[kb * BSTRD + n0];
                    unsigned bh1 = Bs_hi[(kb + 4) * BSTRD + n0];
                    unsigned bl0 = Bs_lo[kb * BSTRD + n0];
                    unsigned bl1 = Bs_lo[(kb + 4) * BSTRD + n0];
                    mma_tf32(acc[j], al, bh0, bh1);
                    mma_tf32(acc[j], ah, bl0, bl1);
                    mma_tf32(acc[j], ah, bh0, bh1);
                }
            }
        }
    }

    int r0 = block_row + (w << 4) + (lane >> 2);
    int r1 = r0 + 8;
    #pragma unroll
    for (int j = 0; j < 5; j++) {
        int c = (j << 3) + ((lane & 3) << 1);
        float bi0 = bias[c], bi1 = bias[c + 1];
        if (r0 < NNODES) {
            out[(size_t)r0 * NCLASS + c]     = acc[j][0] + bi0;
            out[(size_t)r0 * NCLASS + c + 1] = acc[j][1] + bi1;
        }
        if (r1 < NNODES) {
            out[(size_t)r1 * NCLASS + c]     = acc[j][2] + bi0;
            out[(size_t)r1 * NCLASS + c + 1] = acc[j][3] + bi1;
        }
    }
}

// ---------------- log_softmax in place, warp per row ----------------
__global__ void k_logsoftmax(float* __restrict__ out) {
    int w    = (blockIdx.x * blockDim.x + threadIdx.x) >> 5;
    int lane = threadIdx.x & 31;
    if (w >= NNODES) return;
    float* row = out + (size_t)w * NCLASS;
    float v0 = (lane < NCLASS)      ? row[lane]      : -1e30f;
    float v1 = (lane + 32 < NCLASS) ? row[lane + 32] : -1e30f;
    float m = fmaxf(v0, v1);
    #pragma unroll
    for (int o = 16; o; o >>= 1) m = fmaxf(m, __shfl_xor_sync(0xFFFFFFFFu, m, o));
    float s = ((lane < NCLASS) ? expf(v0 - m) : 0.f) +
              ((lane + 32 < NCLASS) ? expf(v1 - m) : 0.f);
    #pragma unroll
    for (int o = 16; o; o >>= 1) s += __shfl_xor_sync(0xFFFFFFFFu, s, o);
    float l = m + logf(s);
    if (lane < NCLASS)      row[lane]      = v0 - l;
    if (lane + 32 < NCLASS) row[lane + 32] = v1 - l;
}

// ---------------- launch ----------------
extern "C" void kernel_launch(void* const* d_in, const int* in_sizes, int n_in,
                              void* d_out, int out_size) {
    const float* x      = (const float*)d_in[0];
    const int*   ei     = (const int*)  d_in[1];
    const float* enc_Wl = (const float*)d_in[2];
    const float* enc_Wr = (const float*)d_in[3];
    const float* enc_b  = (const float*)d_in[4];
    const float* lay_Wl = (const float*)d_in[5];
    const float* lay_Wr = (const float*)d_in[6];
    const float* lay_b  = (const float*)d_in[7];
    const float* dec_Wl = (const float*)d_in[8];
    const float* dec_Wr = (const float*)d_in[9];
    const float* dec_b  = (const float*)d_in[10];
    float* out = (float*)d_out;

    float *agg, *hA, *hB;
    cudaGetSymbolAddress((void**)&agg, g_agg);
    cudaGetSymbolAddress((void**)&hA,  g_hA);
    cudaGetSymbolAddress((void**)&hB,  g_hB);

    const int ZB = (NNODES + 255) / 256;
    const int EB = (NEDGES + 255) / 256;
    const int AGGB = (NNODES * 32 + 255) / 256;   // warp per node
    const int MB = (NNODES + 127) / 128;          // GEMM row-tiles

    k_zero<<<ZB, 256>>>();
    k_hist<<<EB, 256>>>(ei);
    k_scan<<<1, 1024>>>();
    k_fill<<<EB, 256>>>(ei);

    // encoder
    k_aggregate<<<AGGB, 256>>>(x, agg);
    k_gemm128<<<MB, 256>>>(agg, x, enc_Wl, enc_Wr, enc_b, hA);
    // layer 0
    k_aggregate<<<AGGB, 256>>>(hA, agg);
    k_gemm128<<<MB, 256>>>(agg, hA, lay_Wl, lay_Wr, lay_b, hB);
    // layer 1
    k_aggregate<<<AGGB, 256>>>(hB, agg);
    k_gemm128<<<MB, 256>>>(agg, hB, lay_Wl + HFEAT * HFEAT, lay_Wr + HFEAT * HFEAT,
                           lay_b + HFEAT, hA);
    // decoder + log_softmax
    k_aggregate<<<AGGB, 256>>>(hA, agg);
    k_gemm_dec<<<MB, 256>>>(agg, hA, dec_Wl, dec_Wr, dec_b, out);
    k_logsoftmax<<<AGGB, 256>>>(out);
}

// round 4
// speedup vs baseline: 1.5601x; 1.1529x over previous
#include <cuda_runtime.h>

#define NNODES 50000
#define NEDGES 600000
#define HFEAT  128
#define NCLASS 40
#define NEG_SLOPE 0.1f
#define NBLK 196   // ceil(NNODES/256)

// ---------------- device scratch (static, allocation-free) ----------------
__device__ int   g_deg[NNODES];
__device__ int   g_fill[NNODES];
__device__ int   g_rowptr[NNODES + 1];
__device__ int   g_col[NEDGES];
__device__ float g_inv[NNODES];
__device__ int   g_btot[NBLK];
__device__ int   g_boff[NBLK];
__device__ float g_agg[(size_t)NNODES * HFEAT];
__device__ float g_hA [(size_t)NNODES * HFEAT];
__device__ float g_hB [(size_t)NNODES * HFEAT];
// pre-split weights: [encWl|encWr|lay0Wl|lay0Wr|lay1Wl|lay1Wr] each 16384
__device__ __align__(16) unsigned g_Whi[6 * 16384];
__device__ __align__(16) unsigned g_Wlo[6 * 16384];
// dec: [decWl|decWr] each 5120
__device__ __align__(16) unsigned g_Dhi[2 * 5120];
__device__ __align__(16) unsigned g_Dlo[2 * 5120];

// ---------------- helpers ----------------
__device__ __forceinline__ void tf32_split(float v, unsigned& hi, unsigned& lo) {
    unsigned h;
    asm("cvt.rna.tf32.f32 %0, %1;" : "=r"(h) : "f"(v));
    float hf = __uint_as_float(h);
    float lf = v - hf;
    unsigned l;
    asm("cvt.rna.tf32.f32 %0, %1;" : "=r"(l) : "f"(lf));
    hi = h; lo = l;
}

__device__ __forceinline__ void mma_tf32(float* d, const unsigned* a, unsigned b0, unsigned b1) {
    asm volatile(
        "mma.sync.aligned.m16n8k8.row.col.f32.tf32.tf32.f32 "
        "{%0,%1,%2,%3}, {%4,%5,%6,%7}, {%8,%9}, {%0,%1,%2,%3};"
        : "+f"(d[0]), "+f"(d[1]), "+f"(d[2]), "+f"(d[3])
        : "r"(a[0]), "r"(a[1]), "r"(a[2]), "r"(a[3]), "r"(b0), "r"(b1));
}

// ---------------- weight pre-split ----------------
__global__ void k_splitW(const float* __restrict__ eWl, const float* __restrict__ eWr,
                         const float* __restrict__ lWl, const float* __restrict__ lWr,
                         const float* __restrict__ dWl, const float* __restrict__ dWr)
{
    int i = blockIdx.x * blockDim.x + threadIdx.x;
    if (i < 6 * 16384) {
        int m = i >> 14, off = i & 16383;
        const float* src = (m == 0) ? eWl : (m == 1) ? eWr : (m == 2) ? lWl :
                           (m == 3) ? lWr : (m == 4) ? lWl + 16384 : lWr + 16384;
        unsigned h, l;
        tf32_split(src[off], h, l);
        g_Whi[i] = h; g_Wlo[i] = l;
    } else if (i < 6 * 16384 + 2 * 5120) {
        int j = i - 6 * 16384;
        const float* src = (j < 5120) ? dWl : dWr;
        int off = (j < 5120) ? j : j - 5120;
        unsigned h, l;
        tf32_split(src[off], h, l);
        g_Dhi[j] = h; g_Dlo[j] = l;
    }
}

// ---------------- CSR build ----------------
__global__ void k_zero() {
    int i = blockIdx.x * blockDim.x + threadIdx.x;
    if (i < NNODES) { g_deg[i] = 0; g_fill[i] = 0; }
}

__global__ void k_hist(const int* __restrict__ ei) {
    int e = blockIdx.x * blockDim.x + threadIdx.x;
    if (e < NEDGES) atomicAdd(&g_deg[ei[NEDGES + e]], 1);
}

// parallel scan, stage 1: block-local inclusive scan, write exclusive + block totals
__global__ void k_scan1() {
    __shared__ int wsum[8];
    int b = blockIdx.x, t = threadIdx.x;
    int idx = (b << 8) + t;
    int v = (idx < NNODES) ? g_deg[idx] : 0;
    int x = v;
    #pragma unroll
    for (int o = 1; o < 32; o <<= 1) {
        int y = __shfl_up_sync(0xFFFFFFFFu, x, o);
        if ((t & 31) >= o) x += y;
    }
    if ((t & 31) == 31) wsum[t >> 5] = x;
    __syncthreads();
    if (t == 0) {
        int c = 0;
        #pragma unroll
        for (int i = 0; i < 8; i++) { int y = wsum[i]; wsum[i] = c; c += y; }
    }
    __syncthreads();
    int incl = x + wsum[t >> 5];
    if (idx < NNODES) {
        g_rowptr[idx] = incl - v;
        g_inv[idx] = 1.0f / fmaxf((float)v, 1.0f);
    }
    if (t == 255) g_btot[b] = incl;
}

// stage 2: scan the 196 block totals (one block)
__global__ void k_scan2() {
    __shared__ int wsum[8];
    int t = threadIdx.x;
    int v = (t < NBLK) ? g_btot[t] : 0;
    int x = v;
    #pragma unroll
    for (int o = 1; o < 32; o <<= 1) {
        int y = __shfl_up_sync(0xFFFFFFFFu, x, o);
        if ((t & 31) >= o) x += y;
    }
    if ((t & 31) == 31) wsum[t >> 5] = x;
    __syncthreads();
    if (t == 0) {
        int c = 0;
        #pragma unroll
        for (int i = 0; i < 8; i++) { int y = wsum[i]; wsum[i] = c; c += y; }
    }
    __syncthreads();
    int incl = x + wsum[t >> 5];
    if (t < NBLK) g_boff[t] = incl - v;
    if (t == 255) g_rowptr[NNODES] = incl;
}

// stage 3: add block offsets
__global__ void k_scan3() {
    int b = blockIdx.x, t = threadIdx.x;
    int idx = (b << 8) + t;
    if (idx < NNODES) g_rowptr[idx] += g_boff[b];
}

__global__ void k_fill(const int* __restrict__ ei) {
    int e = blockIdx.x * blockDim.x + threadIdx.x;
    if (e < NEDGES) {
        int dst = ei[NEDGES + e];
        int pos = g_rowptr[dst] + atomicAdd(&g_fill[dst], 1);
        g_col[pos] = ei[e];
    }
}

// ---------------- mean aggregation: warp per destination node ----------------
__global__ void k_aggregate(const float* __restrict__ in, float* __restrict__ out) {
    int gw   = (blockIdx.x * blockDim.x + threadIdx.x) >> 5;
    int lane = threadIdx.x & 31;
    if (gw >= NNODES) return;
    int s = g_rowptr[gw], e = g_rowptr[gw + 1];
    float4 acc = make_float4(0.f, 0.f, 0.f, 0.f);
    int i = s;
    for (; i + 1 < e; i += 2) {
        int s0 = g_col[i], s1 = g_col[i + 1];
        float4 v0 = *(const float4*)(in + (size_t)s0 * HFEAT + lane * 4);
        float4 v1 = *(const float4*)(in + (size_t)s1 * HFEAT + lane * 4);
        acc.x += v0.x + v1.x; acc.y += v0.y + v1.y;
        acc.z += v0.z + v1.z; acc.w += v0.w + v1.w;
    }
    if (i < e) {
        int s0 = g_col[i];
        float4 v0 = *(const float4*)(in + (size_t)s0 * HFEAT + lane * 4);
        acc.x += v0.x; acc.y += v0.y; acc.z += v0.z; acc.w += v0.w;
    }
    float inv = g_inv[gw];
    float4 r = make_float4(acc.x * inv, acc.y * inv, acc.z * inv, acc.w * inv);
    *(float4*)(out + (size_t)gw * HFEAT + lane * 4) = r;
}

// ---------------- SAGE GEMM, 3xTF32, pipelined, pre-split W ----------------
#define ASTR 20
#define BSTR 132

__global__ void __launch_bounds__(256, 2) k_gemm128(
    const float* __restrict__ A1, const float* __restrict__ A2,
    const unsigned* __restrict__ Whi0, const unsigned* __restrict__ Wlo0,
    const unsigned* __restrict__ Whi1, const unsigned* __restrict__ Wlo1,
    const float* __restrict__ bias, float* __restrict__ out)
{
    __shared__ unsigned As_hi[128 * ASTR];
    __shared__ unsigned As_lo[128 * ASTR];
    __shared__ unsigned Bs_hi[16 * BSTR];
    __shared__ unsigned Bs_lo[16 * BSTR];

    int t = threadIdx.x;
    int lane = t & 31;
    int w = t >> 5;
    int rg = w >> 1;      // row group 0..3 (32 rows each)
    int cg = w & 1;       // col group 0..1 (64 cols each)
    int block_row = blockIdx.x * 128;

    float acc[2][8][4];
    #pragma unroll
    for (int i = 0; i < 2; i++)
        #pragma unroll
        for (int j = 0; j < 8; j++)
            #pragma unroll
            for (int q = 0; q < 4; q++) acc[i][j][q] = 0.f;

    float4 avP[2];
    uint4  bhP[2], blP[2];

    auto prefetch = [&](int c) {
        int pn = c >> 3, k0 = (c & 7) << 4;
        const float*    A  = pn ? A2 : A1;
        const unsigned* Wh = pn ? Whi1 : Whi0;
        const unsigned* Wl = pn ? Wlo1 : Wlo0;
        #pragma unroll
        for (int i = 0; i < 2; i++) {
            int idx = t + (i << 8);
            int r = idx >> 2, kk = (idx & 3) << 2;
            int gr = block_row + r;
            avP[i] = (gr < NNODES) ? *(const float4*)(A + (size_t)gr * 128 + k0 + kk)
                                   : make_float4(0.f, 0.f, 0.f, 0.f);
            int kb = idx >> 5, n = (idx & 31) << 2;
            bhP[i] = *(const uint4*)(Wh + (size_t)(k0 + kb) * 128 + n);
            blP[i] = *(const uint4*)(Wl + (size_t)(k0 + kb) * 128 + n);
        }
    };

    prefetch(0);

    #pragma unroll 1
    for (int c = 0; c < 16; ++c) {
        __syncthreads();
        #pragma unroll
        for (int i = 0; i < 2; i++) {
            int idx = t + (i << 8);
            int r = idx >> 2, kk = (idx & 3) << 2;
            uint4 h, l;
            tf32_split(avP[i].x, h.x, l.x);
            tf32_split(avP[i].y, h.y, l.y);
            tf32_split(avP[i].z, h.z, l.z);
            tf32_split(avP[i].w, h.w, l.w);
            *(uint4*)&As_hi[r * ASTR + kk] = h;
            *(uint4*)&As_lo[r * ASTR + kk] = l;
            int kb = idx >> 5, n = (idx & 31) << 2;
            *(uint4*)&Bs_hi[kb * BSTR + n] = bhP[i];
            *(uint4*)&Bs_lo[kb * BSTR + n] = blP[i];
        }
        __syncthreads();
        if (c < 15) prefetch(c + 1);

        #pragma unroll
        for (int ks = 0; ks < 2; ks++) {
            unsigned ah[2][4], al[2][4];
            int kc = (ks << 3) + (lane & 3);
            int rb = (rg << 5) + (lane >> 2);
            #pragma unroll
            for (int i = 0; i < 2; i++) {
                int r0 = rb + (i << 4);
                ah[i][0] = As_hi[r0 * ASTR + kc];
                ah[i][1] = As_hi[(r0 + 8) * ASTR + kc];
                ah[i][2] = As_hi[r0 * ASTR + kc + 4];
                ah[i][3] = As_hi[(r0 + 8) * ASTR + kc + 4];
                al[i][0] = As_lo[r0 * ASTR + kc];
                al[i][1] = As_lo[(r0 + 8) * ASTR + kc];
                al[i][2] = As_lo[r0 * ASTR + kc + 4];
                al[i][3] = As_lo[(r0 + 8) * ASTR + kc + 4];
            }
            #pragma unroll
            for (int j = 0; j < 8; j++) {
                int n0 = (cg << 6) + (j << 3) + (lane >> 2);
                int kb = (ks << 3) + (lane & 3);
                unsigned bh0 = Bs_hi[kb * BSTR + n0];
                unsigned bh1 = Bs_hi[(kb + 4) * BSTR + n0];
                unsigned bl0 = Bs_lo[kb * BSTR + n0];
                unsigned bl1 = Bs_lo[(kb + 4) * BSTR + n0];
                #pragma unroll
                for (int i = 0; i < 2; i++) {
                    mma_tf32(acc[i][j], al[i], bh0, bh1);
                    mma_tf32(acc[i][j], ah[i], bl0, bl1);
                    mma_tf32(acc[i][j], ah[i], bh0, bh1);
                }
            }
        }
    }

    // epilogue: bias + leaky relu
    #pragma unroll
    for (int i = 0; i < 2; i++) {
        int r0 = block_row + (rg << 5) + (i << 4) + (lane >> 2);
        #pragma unroll
        for (int j = 0; j < 8; j++) {
            int c = (cg << 6) + (j << 3) + ((lane & 3) << 1);
            float bi0 = bias[c], bi1 = bias[c + 1];
            if (r0 < NNODES) {
                float v0 = acc[i][j][0] + bi0;
                float v1 = acc[i][j][1] + bi1;
                v0 = v0 > 0.f ? v0 : NEG_SLOPE * v0;
                v1 = v1 > 0.f ? v1 : NEG_SLOPE * v1;
                out[(size_t)r0 * 128 + c] = v0;
                out[(size_t)r0 * 128 + c + 1] = v1;
            }
            int r1 = r0 + 8;
            if (r1 < NNODES) {
                float v2 = acc[i][j][2] + bi0;
                float v3 = acc[i][j][3] + bi1;
                v2 = v2 > 0.f ? v2 : NEG_SLOPE * v2;
                v3 = v3 > 0.f ? v3 : NEG_SLOPE * v3;
                out[(size_t)r1 * 128 + c] = v2;
                out[(size_t)r1 * 128 + c + 1] = v3;
            }
        }
    }
}

// ---------------- decoder GEMM + fused log_softmax ----------------
#define BSTRD 44

__global__ void __launch_bounds__(256, 2) k_gemm_dec(
    const float* __restrict__ A1, const float* __restrict__ A2,
    const unsigned* __restrict__ Dhi0, const unsigned* __restrict__ Dlo0,
    const unsigned* __restrict__ Dhi1, const unsigned* __restrict__ Dlo1,
    const float* __restrict__ bias, float* __restrict__ out)
{
    __shared__ unsigned As_hi[128 * ASTR];
    __shared__ unsigned As_lo[128 * ASTR];
    __shared__ unsigned Bs_hi[16 * BSTRD];
    __shared__ unsigned Bs_lo[16 * BSTRD];

    int t = threadIdx.x;
    int lane = t & 31;
    int w = t >> 5;               // warp 0..7, owns 16 rows
    int block_row = blockIdx.x * 128;

    float acc[5][4];
    #pragma unroll
    for (int j = 0; j < 5; j++)
        #pragma unroll
        for (int q = 0; q < 4; q++) acc[j][q] = 0.f;

    float4 avP[2];
    uint4  bhP, blP;
    bool bload = t < 160;

    auto prefetch = [&](int c) {
        int pn = c >> 3, k0 = (c & 7) << 4;
        const float*    A  = pn ? A2 : A1;
        const unsigned* Dh = pn ? Dhi1 : Dhi0;
        const unsigned* Dl = pn ? Dlo1 : Dlo0;
        #pragma unroll
        for (int i = 0; i < 2; i++) {
            int idx = t + (i << 8);
            int r = idx >> 2, kk = (idx & 3) << 2;
            int gr = block_row + r;
            avP[i] = (gr < NNODES) ? *(const float4*)(A + (size_t)gr * 128 + k0 + kk)
                                   : make_float4(0.f, 0.f, 0.f, 0.f);
        }
        if (bload) {
            int kk = t / 10, n = (t % 10) << 2;
            bhP = *(const uint4*)(Dh + (size_t)(k0 + kk) * NCLASS + n);
            blP = *(const uint4*)(Dl + (size_t)(k0 + kk) * NCLASS + n);
        }
    };

    prefetch(0);

    #pragma unroll 1
    for (int c = 0; c < 16; ++c) {
        __syncthreads();
        #pragma unroll
        for (int i = 0; i < 2; i++) {
            int idx = t + (i << 8);
            int r = idx >> 2, kk = (idx & 3) << 2;
            uint4 h, l;
            tf32_split(avP[i].x, h.x, l.x);
            tf32_split(avP[i].y, h.y, l.y);
            tf32_split(avP[i].z, h.z, l.z);
            tf32_split(avP[i].w, h.w, l.w);
            *(uint4*)&As_hi[r * ASTR + kk] = h;
            *(uint4*)&As_lo[r * ASTR + kk] = l;
        }
        if (bload) {
            int kk = t / 10, n = (t % 10) << 2;
            *(uint4*)&Bs_hi[kk * BSTRD + n] = bhP;
            *(uint4*)&Bs_lo[kk * BSTRD + n] = blP;
        }
        __syncthreads();
        if (c < 15) prefetch(c + 1);

        #pragma unroll
        for (int ks = 0; ks < 2; ks++) {
            unsigned ah[4], al[4];
            int kc = (ks << 3) + (lane & 3);
            int r0 = (w << 4) + (lane >> 2);
            ah[0] = As_hi[r0 * ASTR + kc];
            ah[1] = As_hi[(r0 + 8) * ASTR + kc];
            ah[2] = As_hi[r0 * ASTR + kc + 4];
            ah[3] = As_hi[(r0 + 8) * ASTR + kc + 4];
            al[0] = As_lo[r0 * ASTR + kc];
            al[1] = As_lo[(r0 + 8) * ASTR + kc];
            al[2] = As_lo[r0 * ASTR + kc + 4];
            al[3] = As_lo[(r0 + 8) * ASTR + kc + 4];
            #pragma unroll
            for (int j = 0; j < 5; j++) {
                int n0 = (j << 3) + (lane >> 2);
                int kb = (ks << 3) + (lane & 3);
                unsigned bh0 = Bs_hi[kb * BSTRD + n0];
                unsigned bh1 = Bs_hi[(kb + 4) * BSTRD + n0];
                unsigned bl0 = Bs_lo[kb * BSTRD + n0];
                unsigned bl1 = Bs_lo[(kb + 4) * BSTRD + n0];
                mma_tf32(acc[j], al, bh0, bh1);
                mma_tf32(acc[j], ah, bl0, bl1);
                mma_tf32(acc[j], ah, bh0, bh1);
            }
        }
    }

    // fused epilogue: bias + log_softmax. A quad of lanes (same lane>>2) holds
    // all 40 cols of rows r0 and r1; reduce with 2 quad shuffles.
    float va0[10], va1[10];
    float m0 = -1e30f, m1 = -1e30f;
    #pragma unroll
    for (int j = 0; j < 5; j++) {
        int c = (j << 3) + ((lane & 3) << 1);
        float bi0 = bias[c], bi1 = bias[c + 1];
        va0[2 * j]     = acc[j][0] + bi0;
        va0[2 * j + 1] = acc[j][1] + bi1;
        va1[2 * j]     = acc[j][2] + bi0;
        va1[2 * j + 1] = acc[j][3] + bi1;
        m0 = fmaxf(m0, fmaxf(va0[2 * j], va0[2 * j + 1]));
        m1 = fmaxf(m1, fmaxf(va1[2 * j], va1[2 * j + 1]));
    }
    #pragma unroll
    for (int o = 1; o < 4; o <<= 1) {
        m0 = fmaxf(m0, __shfl_xor_sync(0xFFFFFFFFu, m0, o));
        m1 = fmaxf(m1, __shfl_xor_sync(0xFFFFFFFFu, m1, o));
    }
    float s0 = 0.f, s1 = 0.f;
    #pragma unroll
    for (int q = 0; q < 10; q++) {
        s0 += expf(va0[q] - m0);
        s1 += expf(va1[q] - m1);
    }
    #pragma unroll
    for (int o = 1; o < 4; o <<= 1) {
        s0 += __shfl_xor_sync(0xFFFFFFFFu, s0, o);
        s1 += __shfl_xor_sync(0xFFFFFFFFu, s1, o);
    }
    float l0 = m0 + logf(s0);
    float l1 = m1 + logf(s1);

    int r0 = block_row + (w << 4) + (lane >> 2);
    int r1 = r0 + 8;
    #pragma unroll
    for (int j = 0; j < 5; j++) {
        int c = (j << 3) + ((lane & 3) << 1);
        if (r0 < NNODES) {
            out[(size_t)r0 * NCLASS + c]     = va0[2 * j]     - l0;
            out[(size_t)r0 * NCLASS + c + 1] = va0[2 * j + 1] - l0;
        }
        if (r1 < NNODES) {
            out[(size_t)r1 * NCLASS + c]     = va1[2 * j]     - l1;
            out[(size_t)r1 * NCLASS + c + 1] = va1[2 * j + 1] - l1;
        }
    }
}

// ---------------- launch ----------------
extern "C" void kernel_launch(void* const* d_in, const int* in_sizes, int n_in,
                              void* d_out, int out_size) {
    const float* x      = (const float*)d_in[0];
    const int*   ei     = (const int*)  d_in[1];
    const float* enc_Wl = (const float*)d_in[2];
    const float* enc_Wr = (const float*)d_in[3];
    const float* enc_b  = (const float*)d_in[4];
    const float* lay_Wl = (const float*)d_in[5];
    const float* lay_Wr = (const float*)d_in[6];
    const float* lay_b  = (const float*)d_in[7];
    const float* dec_Wl = (const float*)d_in[8];
    const float* dec_Wr = (const float*)d_in[9];
    const float* dec_b  = (const float*)d_in[10];
    float* out = (float*)d_out;

    float *agg, *hA, *hB;
    unsigned *whi, *wlo, *dhi, *dlo;
    cudaGetSymbolAddress((void**)&agg, g_agg);
    cudaGetSymbolAddress((void**)&hA,  g_hA);
    cudaGetSymbolAddress((void**)&hB,  g_hB);
    cudaGetSymbolAddress((void**)&whi, g_Whi);
    cudaGetSymbolAddress((void**)&wlo, g_Wlo);
    cudaGetSymbolAddress((void**)&dhi, g_Dhi);
    cudaGetSymbolAddress((void**)&dlo, g_Dlo);

    const int ZB = (NNODES + 255) / 256;
    const int EB = (NEDGES + 255) / 256;
    const int AGGB = (NNODES * 32 + 255) / 256;   // warp per node
    const int MB = (NNODES + 127) / 128;          // GEMM row-tiles
    const int SW = (6 * 16384 + 2 * 5120 + 255) / 256;

    k_splitW<<<SW, 256>>>(enc_Wl, enc_Wr, lay_Wl, lay_Wr, dec_Wl, dec_Wr);
    k_zero<<<ZB, 256>>>();
    k_hist<<<EB, 256>>>(ei);
    k_scan1<<<NBLK, 256>>>();
    k_scan2<<<1, 256>>>();
    k_scan3<<<NBLK, 256>>>();
    k_fill<<<EB, 256>>>(ei);

    // encoder
    k_aggregate<<<AGGB, 256>>>(x, agg);
    k_gemm128<<<MB, 256>>>(agg, x, whi, wlo, whi + 16384, wlo + 16384, enc_b, hA);
    // layer 0
    k_aggregate<<<AGGB, 256>>>(hA, agg);
    k_gemm128<<<MB, 256>>>(agg, hA, whi + 2 * 16384, wlo + 2 * 16384,
                           whi + 3 * 16384, wlo + 3 * 16384, lay_b, hB);
    // layer 1
    k_aggregate<<<AGGB, 256>>>(hB, agg);
    k_gemm128<<<MB, 256>>>(agg, hB, whi + 4 * 16384, wlo + 4 * 16384,
                           whi + 5 * 16384, wlo + 5 * 16384, lay_b + HFEAT, hA);
    // decoder with fused log_softmax
    k_aggregate<<<AGGB, 256>>>(hA, agg);
    k_gemm_dec<<<MB, 256>>>(agg, hA, dhi, dlo, dhi + 5120, dlo + 5120, dec_b, out);
}